// round 1
// baseline (speedup 1.0000x reference)
#include <cuda_runtime.h>

#define N_PDE   4096
#define WINDOW  327
#define HALF    163
#define RL      20
#define TB      16                 // starts per phase-B block
#define NBLK_B  (N_PDE / TB)       // 256

// Scratch (allocation-free rule: __device__ globals)
__device__ float g_W40[40 * 327];      // combined [resize ; resize∘gradient] operator
__device__ float g_hc[N_PDE * 32];     // per-start branch output folded through cW[:256]

// ---------------------------------------------------------------------------
// Kernel 1: build the 40x327 linear operator matching
// jax.image.resize(method='bilinear', antialias=True) and jnp.gradient.
// ---------------------------------------------------------------------------
__global__ void setup_weights_kernel() {
    __shared__ float R[20 * 327];
    __shared__ float sums[20];
    const float scale     = 20.0f / 327.0f;
    const float inv_scale = 1.0f / scale;

    for (int idx = threadIdx.x; idx < 20 * 327; idx += blockDim.x) {
        int o = idx / 327, i = idx - o * 327;
        float sf = ((float)o + 0.5f) * inv_scale - 0.5f;
        float x  = fabsf(sf - (float)i) * scale;     // antialias: kernel_scale = inv_scale
        R[idx] = fmaxf(0.0f, 1.0f - x);              // triangle kernel
    }
    __syncthreads();
    if (threadIdx.x < 20) {
        float s = 0.0f;
        for (int i = 0; i < 327; i++) s += R[threadIdx.x * 327 + i];
        sums[threadIdx.x] = s;
    }
    __syncthreads();
    for (int idx = threadIdx.x; idx < 20 * 327; idx += blockDim.x) {
        int o = idx / 327;
        R[idx] = R[idx] / sums[o];                   // normalize per output row
    }
    __syncthreads();
    for (int idx = threadIdx.x; idx < 20 * 327; idx += blockDim.x) {
        int o = idx / 327, i = idx - o * 327;
        g_W40[idx] = R[idx];                         // rows 0..19 : resize(err)
        // rows 20..39 : resize(gradient(err)) = R * G, G = central-diff matrix
        float v = 0.0f;
        if (i >= 2)   v += 0.5f * R[o * 327 + i - 1];
        if (i <= 324) v -= 0.5f * R[o * 327 + i + 1];
        if (i == 0)   v -= R[o * 327 + 0];
        if (i == 1)   v += R[o * 327 + 0];
        if (i == 325) v -= R[o * 327 + 326];
        if (i == 326) v += R[o * 327 + 326];
        g_W40[(20 + o) * 327 + i] = v;
    }
}

// ---------------------------------------------------------------------------
// Phase B: per distinct start s (4096 total), compute the branch net and fold
// through cW[:256] into g_hc[s][32]. TB=16 starts per block, 256 threads.
// ---------------------------------------------------------------------------
__device__ __forceinline__ float warp_sum(float v) {
    #pragma unroll
    for (int o = 16; o > 0; o >>= 1) v += __shfl_xor_sync(0xffffffffu, v, o);
    return v;
}

__device__ __forceinline__ void gn_tanh_store(
    float* acc, float* hbuf, float* mu_s, float* rs_s,
    float sc, float bi, int tid)
{
    #pragma unroll
    for (int t = 0; t < TB; t++) hbuf[t * 257 + tid] = acc[t];
    __syncthreads();
    int w = tid >> 5, lane = tid & 31;
    #pragma unroll
    for (int tt = w; tt < TB; tt += 8) {
        float s = 0.0f;
        #pragma unroll
        for (int m = 0; m < 8; m++) s += hbuf[tt * 257 + lane + 32 * m];
        s = warp_sum(s);
        float mu = s * (1.0f / 256.0f);
        float q = 0.0f;
        #pragma unroll
        for (int m = 0; m < 8; m++) {
            float d = hbuf[tt * 257 + lane + 32 * m] - mu;
            q = fmaf(d, d, q);
        }
        q = warp_sum(q);
        if (lane == 0) {
            mu_s[tt] = mu;
            rs_s[tt] = rsqrtf(q * (1.0f / 256.0f) + 1e-6f);
        }
    }
    __syncthreads();
    #pragma unroll
    for (int t = 0; t < TB; t++)
        hbuf[t * 257 + tid] = tanhf((acc[t] - mu_s[t]) * rs_s[t] * sc + bi);
    __syncthreads();
}

__global__ __launch_bounds__(256) void phaseB_kernel(
    const float* __restrict__ z, const float* __restrict__ zt,
    const float* __restrict__ bW0, const float* __restrict__ bb0,
    const float* __restrict__ bs0, const float* __restrict__ bB0,
    const float* __restrict__ bW1, const float* __restrict__ bb1,
    const float* __restrict__ bs1, const float* __restrict__ bB1,
    const float* __restrict__ cW)
{
    __shared__ float e[TB + 352];          // sliding error window (edge-padded)
    __shared__ float obs[TB * 40];
    __shared__ float hbuf[TB * 257];       // padded stride 257
    __shared__ float mu_s[TB], rs_s[TB];

    const int tid = threadIdx.x;
    const int s0  = blockIdx.x * TB;

    // padded error: e[j] = error[clamp(s0 + j - HALF, 0, N_PDE-1)]
    for (int j = tid; j < TB + 352; j += 256) {
        int c = s0 + j - HALF;
        c = min(max(c, 0), N_PDE - 1);
        e[j] = z[c] - zt[c];
    }
    __syncthreads();

    // obs[t][o] = dot(W40[o], window(t))  -- warp per output row, lanes over taps
    {
        const int w = tid >> 5, lane = tid & 31;
        #pragma unroll
        for (int r = 0; r < 5; r++) {
            int o = w + 8 * r;
            float wv[11];
            #pragma unroll
            for (int m = 0; m < 11; m++) {
                int i = lane + 32 * m;
                wv[m] = (i < 327) ? g_W40[o * 327 + i] : 0.0f;
            }
            for (int t = 0; t < TB; t++) {
                float a = 0.0f;
                #pragma unroll
                for (int m = 0; m < 11; m++)
                    a = fmaf(wv[m], e[t + lane + 32 * m], a);
                a = warp_sum(a);
                if (lane == 0) obs[t * 40 + o] = a;
            }
        }
    }
    __syncthreads();

    float acc[TB];

    // branch layer 0: 40 -> 256
    {
        float b = bb0[tid];
        #pragma unroll
        for (int t = 0; t < TB; t++) acc[t] = b;
        #pragma unroll 4
        for (int k = 0; k < 40; k++) {
            float wv = bW0[k * 256 + tid];
            #pragma unroll
            for (int t = 0; t < TB; t++)
                acc[t] = fmaf(obs[t * 40 + k], wv, acc[t]);
        }
    }
    gn_tanh_store(acc, hbuf, mu_s, rs_s, bs0[tid], bB0[tid], tid);

    // branch layer 1: 256 -> 256
    {
        float b = bb1[tid];
        float a2[TB];
        #pragma unroll
        for (int t = 0; t < TB; t++) a2[t] = b;
        for (int k = 0; k < 256; k++) {
            float wv = bW1[k * 256 + tid];
            #pragma unroll
            for (int t = 0; t < TB; t++)
                a2[t] = fmaf(hbuf[t * 257 + k], wv, a2[t]);
        }
        __syncthreads();                   // done reading h0 before gn overwrites
        #pragma unroll
        for (int t = 0; t < TB; t++) acc[t] = a2[t];
    }
    gn_tanh_store(acc, hbuf, mu_s, rs_s, bs1[tid], bB1[tid], tid);

    // fold through cW[:256]: g_hc[s][o] = h1 . cW[:,o]
    #pragma unroll
    for (int r = 0; r < 2; r++) {
        int idx = tid + 256 * r;
        int t = idx >> 5, o = idx & 31;
        float a = 0.0f;
        for (int k = 0; k < 256; k++)
            a = fmaf(hbuf[t * 257 + k], cW[k * 32 + o], a);
        g_hc[(s0 + t) * 32 + o] = a;
    }
}

// ---------------------------------------------------------------------------
// Phase C: per-agent trunk + head. Thread per agent; all small weights in smem.
// ---------------------------------------------------------------------------
__global__ __launch_bounds__(256) void phaseC_kernel(
    const float* __restrict__ xi,
    const float* __restrict__ tW0, const float* __restrict__ tb0,
    const float* __restrict__ tW1, const float* __restrict__ tb1,
    const float* __restrict__ cW,  const float* __restrict__ cb,
    const float* __restrict__ uW,  const float* __restrict__ ub,
    const float* __restrict__ vW,  const float* __restrict__ vb,
    float* __restrict__ out, int nAgents)
{
    __shared__ float sW0[8 * 32];
    __shared__ float sW1[32 * 32];
    __shared__ float sCt[32 * 32];
    __shared__ float sb0[32], sb1[32], scb[32], su[32], sv[32];
    __shared__ float sub, svb;

    const int tid = threadIdx.x;
    if (tid < 256) {
        if (tid < 8 * 32) sW0[tid] = tW0[tid];
        if (tid < 32) {
            sb0[tid] = tb0[tid]; sb1[tid] = tb1[tid]; scb[tid] = cb[tid];
            su[tid]  = uW[tid];  sv[tid]  = vW[tid];
        }
        if (tid == 0) { sub = ub[0]; svb = vb[0]; }
    }
    for (int i = tid; i < 1024; i += 256) {
        sW1[i] = tW1[i];
        sCt[i] = cW[256 * 32 + i];   // trunk rows of cW
    }
    __syncthreads();

    int a = blockIdx.x * 256 + tid;
    if (a >= nAgents) return;

    float x = xi[a];
    int s = (int)(x * 4095.0f);      // matches (xi*(N_PDE-1)).astype(int32)

    const float PI = 3.14159265358979323846f;
    float enc[8];
    {
        float a1 = (x * 1.0f) * PI;
        float a2 = (x * 2.0f) * PI;
        float a4 = (x * 4.0f) * PI;
        float a8 = (x * 8.0f) * PI;
        enc[0] = sinf(a1); enc[1] = sinf(a2); enc[2] = sinf(a4); enc[3] = sinf(a8);
        enc[4] = cosf(a1); enc[5] = cosf(a2); enc[6] = cosf(a4); enc[7] = cosf(a8);
    }

    float t1[32];
    {
        float t0[32];
        #pragma unroll
        for (int j = 0; j < 32; j++) {
            float acc = sb0[j];
            #pragma unroll
            for (int k = 0; k < 8; k++) acc = fmaf(enc[k], sW0[k * 32 + j], acc);
            t0[j] = tanhf(acc);
        }
        #pragma unroll
        for (int j = 0; j < 32; j++) {
            float acc = sb1[j];
            #pragma unroll
            for (int k = 0; k < 32; k++) acc = fmaf(t0[k], sW1[k * 32 + j], acc);
            t1[j] = tanhf(acc);
        }
    }

    float hc[32];
    {
        const float4* hp = reinterpret_cast<const float4*>(g_hc + s * 32);
        #pragma unroll
        for (int q = 0; q < 8; q++) {
            float4 v = hp[q];
            hc[4 * q + 0] = v.x; hc[4 * q + 1] = v.y;
            hc[4 * q + 2] = v.z; hc[4 * q + 3] = v.w;
        }
    }

    float uacc = sub, vacc = svb;
    #pragma unroll
    for (int j = 0; j < 32; j++) {
        float acc = hc[j] + scb[j];
        #pragma unroll
        for (int k = 0; k < 32; k++) acc = fmaf(t1[k], sCt[k * 32 + j], acc);
        float xo = tanhf(acc);
        uacc = fmaf(xo, su[j], uacc);
        vacc = fmaf(xo, sv[j], vacc);
    }

    out[a]           = 40.0f * tanhf(uacc);
    out[a + nAgents] = tanhf(vacc);
}

// ---------------------------------------------------------------------------
extern "C" void kernel_launch(void* const* d_in, const int* in_sizes, int n_in,
                              void* d_out, int out_size) {
    const float* z_curr   = (const float*)d_in[0];
    const float* z_target = (const float*)d_in[1];
    const float* xi_curr  = (const float*)d_in[2];
    const float* bW0 = (const float*)d_in[3];
    const float* bb0 = (const float*)d_in[4];
    const float* bs0 = (const float*)d_in[5];
    const float* bB0 = (const float*)d_in[6];
    const float* bW1 = (const float*)d_in[7];
    const float* bb1 = (const float*)d_in[8];
    const float* bs1 = (const float*)d_in[9];
    const float* bB1 = (const float*)d_in[10];
    const float* tW0 = (const float*)d_in[11];
    const float* tb0 = (const float*)d_in[12];
    const float* tW1 = (const float*)d_in[13];
    const float* tb1 = (const float*)d_in[14];
    const float* cW  = (const float*)d_in[15];
    const float* cb  = (const float*)d_in[16];
    const float* uW  = (const float*)d_in[17];
    const float* ub  = (const float*)d_in[18];
    const float* vW  = (const float*)d_in[19];
    const float* vb  = (const float*)d_in[20];

    const int nAgents = in_sizes[2];

    setup_weights_kernel<<<1, 256>>>();
    phaseB_kernel<<<NBLK_B, 256>>>(z_curr, z_target,
                                   bW0, bb0, bs0, bB0,
                                   bW1, bb1, bs1, bB1, cW);
    phaseC_kernel<<<(nAgents + 255) / 256, 256>>>(xi_curr,
                                                  tW0, tb0, tW1, tb1,
                                                  cW, cb, uW, ub, vW, vb,
                                                  (float*)d_out, nAgents);
}

// round 2
// speedup vs baseline: 1.2129x; 1.2129x over previous
#include <cuda_runtime.h>

#define N_PDE   4096
#define WINDOW  327
#define HALF    163
#define TB      16                 // starts per phase-B block
#define NBLK_B  (N_PDE / TB)       // 256
#define HS      260                // hbuf stride (float4-aligned, conflict-free)

// Scratch (allocation-free rule: __device__ globals)
__device__ float g_hc[N_PDE * 32];     // per-start branch output folded through cW[:256]

// ---------------------------------------------------------------------------
// helpers
// ---------------------------------------------------------------------------
__device__ __forceinline__ float2 fma2(float2 a, float2 b, float2 c) {
    float2 d;
    asm("{\n\t"
        ".reg .b64 ra, rb, rc, rd;\n\t"
        "mov.b64 ra, {%2,%3};\n\t"
        "mov.b64 rb, {%4,%5};\n\t"
        "mov.b64 rc, {%6,%7};\n\t"
        "fma.rn.f32x2 rd, ra, rb, rc;\n\t"
        "mov.b64 {%0,%1}, rd;\n\t"
        "}"
        : "=f"(d.x), "=f"(d.y)
        : "f"(a.x), "f"(a.y), "f"(b.x), "f"(b.y), "f"(c.x), "f"(c.y));
    return d;
}

__device__ __forceinline__ float tanh_fast(float x) {
    float e = __expf(2.0f * x);                 // FMUL + MUFU.EX2
    return 1.0f - __fdividef(2.0f, e + 1.0f);   // FADD + MUFU.RCP + FMA
}

__device__ __forceinline__ float warp_sum(float v) {
    #pragma unroll
    for (int o = 16; o > 0; o >>= 1) v += __shfl_xor_sync(0xffffffffu, v, o);
    return v;
}

// triangle kernel tap (antialiased bilinear downsample), unnormalized
__device__ __forceinline__ float tri(int o, float i) {
    const float scale     = 20.0f / 327.0f;
    const float inv_scale = 327.0f / 20.0f;
    float sf = ((float)o + 0.5f) * inv_scale - 0.5f;
    float x  = fabsf(sf - i) * scale;
    return fmaxf(0.0f, 1.0f - x);
}

// combined [resize ; resize∘gradient] operator element (normalized by sums[])
__device__ __forceinline__ float W40(int o, int i, const float* sums) {
    if (o < 20) return tri(o, (float)i) / sums[o];
    int p = o - 20;
    float v = 0.0f;
    if (i >= 2)   v += 0.5f * tri(p, (float)(i - 1));
    if (i <= 324) v -= 0.5f * tri(p, (float)(i + 1));
    if (i == 0)   v -= tri(p, 0.0f);
    if (i == 1)   v += tri(p, 0.0f);
    if (i == 325) v -= tri(p, 326.0f);
    if (i == 326) v += tri(p, 326.0f);
    return v / sums[p];
}

// ---------------------------------------------------------------------------
// GroupNorm(1) + tanh, writing result into hbuf (stride HS)
// ---------------------------------------------------------------------------
__device__ __forceinline__ void gn_tanh_store(
    float* acc, float* hbuf, float* mu_s, float* rs_s,
    float sc, float bi, int tid)
{
    #pragma unroll
    for (int t = 0; t < TB; t++) hbuf[t * HS + tid] = acc[t];
    __syncthreads();
    int w = tid >> 5, lane = tid & 31;
    #pragma unroll
    for (int tt = w; tt < TB; tt += 8) {
        float s = 0.0f;
        #pragma unroll
        for (int m = 0; m < 8; m++) s += hbuf[tt * HS + lane + 32 * m];
        s = warp_sum(s);
        float mu = s * (1.0f / 256.0f);
        float q = 0.0f;
        #pragma unroll
        for (int m = 0; m < 8; m++) {
            float d = hbuf[tt * HS + lane + 32 * m] - mu;
            q = fmaf(d, d, q);
        }
        q = warp_sum(q);
        if (lane == 0) {
            mu_s[tt] = mu;
            rs_s[tt] = rsqrtf(q * (1.0f / 256.0f) + 1e-6f);
        }
    }
    __syncthreads();
    #pragma unroll
    for (int t = 0; t < TB; t++)
        hbuf[t * HS + tid] = tanh_fast((acc[t] - mu_s[t]) * rs_s[t] * sc + bi);
    __syncthreads();
}

// ---------------------------------------------------------------------------
// Phase B: per distinct start s (4096 total), compute the branch net and fold
// through cW[:256] into g_hc[s][32]. TB=16 starts per block, 256 threads.
// ---------------------------------------------------------------------------
__global__ __launch_bounds__(256) void phaseB_kernel(
    const float* __restrict__ z, const float* __restrict__ zt,
    const float* __restrict__ bW0, const float* __restrict__ bb0,
    const float* __restrict__ bs0, const float* __restrict__ bB0,
    const float* __restrict__ bW1, const float* __restrict__ bb1,
    const float* __restrict__ bs1, const float* __restrict__ bB1,
    const float* __restrict__ cW)
{
    __shared__ float e[TB + 352];          // sliding error window (edge-padded)
    __shared__ float obs[TB * 40];
    __shared__ float hbuf[TB * HS];        // padded stride HS (float4-aligned)
    __shared__ float mu_s[TB], rs_s[TB];
    __shared__ float sums[20];

    const int tid = threadIdx.x;
    const int w = tid >> 5, lane = tid & 31;
    const int s0  = blockIdx.x * TB;

    // padded error: e[j] = error[clamp(s0 + j - HALF, 0, N_PDE-1)]
    for (int j = tid; j < TB + 352; j += 256) {
        int c = s0 + j - HALF;
        c = min(max(c, 0), N_PDE - 1);
        e[j] = z[c] - zt[c];
    }

    // resize-kernel row sums (normalization), computed on the fly
    for (int r = w; r < 20; r += 8) {
        float s = 0.0f;
        for (int i = lane; i < 327; i += 32) s += tri(r, (float)i);
        s = warp_sum(s);
        if (lane == 0) sums[r] = s;
    }
    __syncthreads();

    // obs[t][o] = dot(W40[o], window(t)) — warp per output row, lanes over taps
    #pragma unroll
    for (int r = 0; r < 5; r++) {
        int o = w + 8 * r;
        float wv[11];
        #pragma unroll
        for (int m = 0; m < 11; m++) {
            int i = lane + 32 * m;
            wv[m] = (i < 327) ? W40(o, i, sums) : 0.0f;
        }
        for (int t = 0; t < TB; t++) {
            float a = 0.0f;
            #pragma unroll
            for (int m = 0; m < 11; m++)
                a = fmaf(wv[m], e[t + lane + 32 * m], a);
            a = warp_sum(a);
            if (lane == 0) obs[t * 40 + o] = a;
        }
    }
    __syncthreads();

    float acc[TB];

    // branch layer 0: 40 -> 256, packed f32x2 over k-pairs
    {
        float2 a2[TB];
        #pragma unroll
        for (int t = 0; t < TB; t++) a2[t] = make_float2(0.0f, 0.0f);
        #pragma unroll 2
        for (int kk = 0; kk < 20; kk++) {
            float2 w2 = make_float2(bW0[(2 * kk) * 256 + tid],
                                    bW0[(2 * kk + 1) * 256 + tid]);
            #pragma unroll
            for (int t = 0; t < TB; t++) {
                float2 ov = *reinterpret_cast<const float2*>(&obs[t * 40 + 2 * kk]);
                a2[t] = fma2(ov, w2, a2[t]);
            }
        }
        float b = bb0[tid];
        #pragma unroll
        for (int t = 0; t < TB; t++) acc[t] = a2[t].x + a2[t].y + b;
    }
    gn_tanh_store(acc, hbuf, mu_s, rs_s, bs0[tid], bB0[tid], tid);

    // branch layer 1: 256 -> 256, float4 LDS + packed f32x2
    {
        float2 a2[TB];
        #pragma unroll
        for (int t = 0; t < TB; t++) a2[t] = make_float2(0.0f, 0.0f);
        #pragma unroll 2
        for (int k4 = 0; k4 < 64; k4++) {
            int k = 4 * k4;
            float2 wA = make_float2(bW1[(k + 0) * 256 + tid], bW1[(k + 1) * 256 + tid]);
            float2 wB = make_float2(bW1[(k + 2) * 256 + tid], bW1[(k + 3) * 256 + tid]);
            #pragma unroll
            for (int t = 0; t < TB; t++) {
                float4 hv = *reinterpret_cast<const float4*>(&hbuf[t * HS + k]);
                a2[t] = fma2(make_float2(hv.x, hv.y), wA, a2[t]);
                a2[t] = fma2(make_float2(hv.z, hv.w), wB, a2[t]);
            }
        }
        __syncthreads();                   // done reading h0 before gn overwrites
        float b = bb1[tid];
        #pragma unroll
        for (int t = 0; t < TB; t++) acc[t] = a2[t].x + a2[t].y + b;
    }
    gn_tanh_store(acc, hbuf, mu_s, rs_s, bs1[tid], bB1[tid], tid);

    // fold through cW[:256]: g_hc[s][o] = h1 . cW[:,o]
    #pragma unroll
    for (int r = 0; r < 2; r++) {
        int idx = tid + 256 * r;
        int t = idx >> 5, o = idx & 31;
        float2 a2f = make_float2(0.0f, 0.0f);
        #pragma unroll 2
        for (int k4 = 0; k4 < 64; k4++) {
            int k = 4 * k4;
            float4 hv = *reinterpret_cast<const float4*>(&hbuf[t * HS + k]);
            float c0 = cW[(k + 0) * 32 + o], c1 = cW[(k + 1) * 32 + o];
            float c2 = cW[(k + 2) * 32 + o], c3 = cW[(k + 3) * 32 + o];
            a2f = fma2(make_float2(hv.x, hv.y), make_float2(c0, c1), a2f);
            a2f = fma2(make_float2(hv.z, hv.w), make_float2(c2, c3), a2f);
        }
        g_hc[(s0 + t) * 32 + o] = a2f.x + a2f.y;
    }
}

// ---------------------------------------------------------------------------
// Phase C: 2 agents per thread, packed f32x2 throughout.
// ---------------------------------------------------------------------------
__global__ __launch_bounds__(256) void phaseC_kernel(
    const float* __restrict__ xi,
    const float* __restrict__ tW0, const float* __restrict__ tb0,
    const float* __restrict__ tW1, const float* __restrict__ tb1,
    const float* __restrict__ cW,  const float* __restrict__ cb,
    const float* __restrict__ uW,  const float* __restrict__ ub,
    const float* __restrict__ vW,  const float* __restrict__ vb,
    float* __restrict__ out, int nAgents)
{
    __shared__ float sW0[8 * 32];
    __shared__ float sW1[32 * 32];
    __shared__ float sCt[32 * 32];
    __shared__ float sb0[32], sb1[32], scb[32], su[32], sv[32];
    __shared__ float sub, svb;

    const int tid = threadIdx.x;
    if (tid < 8 * 32) sW0[tid] = tW0[tid];
    if (tid < 32) {
        sb0[tid] = tb0[tid]; sb1[tid] = tb1[tid]; scb[tid] = cb[tid];
        su[tid]  = uW[tid];  sv[tid]  = vW[tid];
    }
    if (tid == 0) { sub = ub[0]; svb = vb[0]; }
    for (int i = tid; i < 1024; i += 256) {
        sW1[i] = tW1[i];
        sCt[i] = cW[256 * 32 + i];   // trunk rows of cW
    }
    __syncthreads();

    int a0 = blockIdx.x * 512 + tid;
    int a1 = a0 + 256;
    if (a0 >= nAgents) return;
    bool has1 = (a1 < nAgents);

    float x0 = xi[a0];
    float x1 = has1 ? xi[a1] : x0;
    int s_0 = (int)(x0 * 4095.0f);
    int s_1 = (int)(x1 * 4095.0f);

    const float PI = 3.14159265358979323846f;
    float2 enc[8];
    {
        float p0 = x0 * PI, p1 = x1 * PI;
        enc[0] = make_float2(__sinf(p0),        __sinf(p1));
        enc[1] = make_float2(__sinf(2.0f * p0), __sinf(2.0f * p1));
        enc[2] = make_float2(__sinf(4.0f * p0), __sinf(4.0f * p1));
        enc[3] = make_float2(__sinf(8.0f * p0), __sinf(8.0f * p1));
        enc[4] = make_float2(__cosf(p0),        __cosf(p1));
        enc[5] = make_float2(__cosf(2.0f * p0), __cosf(2.0f * p1));
        enc[6] = make_float2(__cosf(4.0f * p0), __cosf(4.0f * p1));
        enc[7] = make_float2(__cosf(8.0f * p0), __cosf(8.0f * p1));
    }

    // trunk
    float2 t1[32];
    {
        float2 t0[32];
        #pragma unroll
        for (int j = 0; j < 32; j++) {
            float2 acc = make_float2(sb0[j], sb0[j]);
            #pragma unroll
            for (int k = 0; k < 8; k++) {
                float wv = sW0[k * 32 + j];
                acc = fma2(enc[k], make_float2(wv, wv), acc);
            }
            t0[j] = make_float2(tanh_fast(acc.x), tanh_fast(acc.y));
        }
        #pragma unroll
        for (int j = 0; j < 32; j++) {
            float2 acc = make_float2(sb1[j], sb1[j]);
            #pragma unroll
            for (int k = 0; k < 32; k++) {
                float wv = sW1[k * 32 + j];
                acc = fma2(t0[k], make_float2(wv, wv), acc);
            }
            t1[j] = make_float2(tanh_fast(acc.x), tanh_fast(acc.y));
        }
    }

    // head: hc + cb + t1 @ Ct, then tanh, then u/v dots
    const float4* hp0 = reinterpret_cast<const float4*>(g_hc + s_0 * 32);
    const float4* hp1 = reinterpret_cast<const float4*>(g_hc + s_1 * 32);

    float2 uacc = make_float2(sub, sub);
    float2 vacc = make_float2(svb, svb);
    #pragma unroll
    for (int q = 0; q < 8; q++) {
        float4 h0 = hp0[q];
        float4 h1 = hp1[q];
        const float* h0p = &h0.x;
        const float* h1p = &h1.x;
        #pragma unroll
        for (int jj = 0; jj < 4; jj++) {
            int j = 4 * q + jj;
            float2 acc = make_float2(h0p[jj] + scb[j], h1p[jj] + scb[j]);
            #pragma unroll
            for (int k = 0; k < 32; k++) {
                float wv = sCt[k * 32 + j];
                acc = fma2(t1[k], make_float2(wv, wv), acc);
            }
            float2 xo = make_float2(tanh_fast(acc.x), tanh_fast(acc.y));
            uacc = fma2(xo, make_float2(su[j], su[j]), uacc);
            vacc = fma2(xo, make_float2(sv[j], sv[j]), vacc);
        }
    }

    out[a0]           = 40.0f * tanh_fast(uacc.x);
    out[a0 + nAgents] = tanh_fast(vacc.x);
    if (has1) {
        out[a1]           = 40.0f * tanh_fast(uacc.y);
        out[a1 + nAgents] = tanh_fast(vacc.y);
    }
}

// ---------------------------------------------------------------------------
extern "C" void kernel_launch(void* const* d_in, const int* in_sizes, int n_in,
                              void* d_out, int out_size) {
    const float* z_curr   = (const float*)d_in[0];
    const float* z_target = (const float*)d_in[1];
    const float* xi_curr  = (const float*)d_in[2];
    const float* bW0 = (const float*)d_in[3];
    const float* bb0 = (const float*)d_in[4];
    const float* bs0 = (const float*)d_in[5];
    const float* bB0 = (const float*)d_in[6];
    const float* bW1 = (const float*)d_in[7];
    const float* bb1 = (const float*)d_in[8];
    const float* bs1 = (const float*)d_in[9];
    const float* bB1 = (const float*)d_in[10];
    const float* tW0 = (const float*)d_in[11];
    const float* tb0 = (const float*)d_in[12];
    const float* tW1 = (const float*)d_in[13];
    const float* tb1 = (const float*)d_in[14];
    const float* cW  = (const float*)d_in[15];
    const float* cb  = (const float*)d_in[16];
    const float* uW  = (const float*)d_in[17];
    const float* ub  = (const float*)d_in[18];
    const float* vW  = (const float*)d_in[19];
    const float* vb  = (const float*)d_in[20];

    const int nAgents = in_sizes[2];

    phaseB_kernel<<<NBLK_B, 256>>>(z_curr, z_target,
                                   bW0, bb0, bs0, bB0,
                                   bW1, bb1, bs1, bB1, cW);
    phaseC_kernel<<<(nAgents + 511) / 512, 256>>>(xi_curr,
                                                  tW0, tb0, tW1, tb1,
                                                  cW, cb, uW, ub, vW, vb,
                                                  (float*)d_out, nAgents);
}